// round 16
// baseline (speedup 1.0000x reference)
#include <cuda_runtime.h>
#include <math.h>

#define BB 256
#define TIN 49
#define TOUT 25
#define NB 24
#define HH 128
#define FIVEH 640
#define KTOT 384

#define WCHUNK_FLOATS 5120  // one (lj,kc32,ht) B chunk: 5 gates x 32 cols x 4 tg x 8 s
#define NPP (NB * 400)      // 9600 prepass items
#define NWF 19200           // wavefront items
#define WF_CTAS 96          // dedicated chain-runner CTAs

// ---------------- device scratch ----------------
__device__ float g_Wfrag[48 * 12 * 4 * WCHUNK_FLOATS];   // 45 MB fragment weights
__device__ float g_P0[BB * TOUT * NB * FIVEH];
__device__ float g_h0[TOUT * NB * BB * HH];       // layer-0 h (tf32-rounded)
__device__ float g_c0[TOUT * NB * BB * HH];       // layer-0 c (full)
__device__ float g_h1r[TOUT * NB * BB * HH];      // layer-1 h rounded shadow
__device__ float g_rowh[2 * NB * BB * HH];
__device__ float g_rowh_r[2 * NB * BB * HH];
__device__ float g_rowc[NB * BB * HH];
__device__ float g_colh_r[BB * HH];
__device__ float g_colc[BB * HH];
// dataflow state
__device__ int g_fP0q[NB][4];             // per (j, b-quarter), target 100
__device__ int g_fcell[2][TOUT][NB][4];   // [l][t][j][mt], target 4
__device__ int g_qwf;
__device__ int g_qpp;

// ---------------- helpers ----------------
__device__ __forceinline__ float sigm(float x) { return 1.0f / (1.0f + __expf(-x)); }
__device__ __forceinline__ float tanh_fast(float x) { return 2.0f / (1.0f + __expf(-2.0f * x)) - 1.0f; }

__device__ __forceinline__ unsigned f2tf32(float v) {
    unsigned u;
    asm("cvt.rna.tf32.f32 %0, %1;" : "=r"(u) : "f"(v));
    return u;
}
__device__ __forceinline__ float f2tf32f(float v) { return __uint_as_float(f2tf32(v)); }

__device__ __forceinline__ void mma_tf32(float* c, const unsigned* a, unsigned b0, unsigned b1) {
    asm volatile(
        "mma.sync.aligned.m16n8k8.row.col.f32.tf32.tf32.f32 "
        "{%0,%1,%2,%3}, {%4,%5,%6,%7}, {%8,%9}, {%0,%1,%2,%3};\n"
        : "+f"(c[0]), "+f"(c[1]), "+f"(c[2]), "+f"(c[3])
        : "r"(a[0]), "r"(a[1]), "r"(a[2]), "r"(a[3]), "r"(b0), "r"(b1));
}

__device__ __forceinline__ void cp16(float* dst_smem, const float* src_gmem) {
    unsigned d = (unsigned)__cvta_generic_to_shared(dst_smem);
    asm volatile("cp.async.cg.shared.global [%0], [%1], 16;\n" ::"r"(d), "l"(src_gmem));
}
__device__ __forceinline__ void cp_commit() { asm volatile("cp.async.commit_group;\n"); }
template <int N>
__device__ __forceinline__ void cp_wait() { asm volatile("cp.async.wait_group %0;\n" ::"n"(N)); }

__device__ __forceinline__ void spin_flag(const int* f, int target) {
    while (*(volatile const int*)f < target) __nanosleep(20);
}

// ---------------- prep: fragment-major weight pack (+ flag zeroing in block 0) ----------------
__global__ void prep_wfrag(const float* __restrict__ U, const float* __restrict__ Wt,
                           const float* __restrict__ Ws) {
    __shared__ float tile[32][33];
    int bx = blockIdx.x;
    int gate = bx % 5;
    int ht = (bx / 5) & 3;
    int kc = (bx / 20) % 12;
    int lj = bx / 240;
    int tx = threadIdx.x & 31, ty = threadIdx.x >> 5;

    const float* src;
    int kbase;
    if (kc < 4) { src = U; kbase = kc * 32; }
    else if (kc < 8) { src = Wt; kbase = (kc - 4) * 32; }
    else { src = Ws; kbase = (kc - 8) * 32; }
    int n0 = gate * 128 + ht * 32;

    for (int kk = ty; kk < 32; kk += 4) {
        float v = src[((size_t)lj * HH + kbase + kk) * FIVEH + n0 + tx];
        tile[kk][tx] = f2tf32f(v);
    }
    __syncthreads();
    float* out = g_Wfrag + ((size_t)(lj * 12 + kc) * 4 + ht) * WCHUNK_FLOATS + gate * 1024;
    int q = tx;
    int kk = (q >> 3) + ((q & 7) << 2);  // tg = q>>3, s = q&7, k-row = tg + 4s
    for (int hh = ty; hh < 32; hh += 4) {
        out[hh * 32 + q] = tile[kk][hh];
    }
    // block 0 zeroes dataflow state (stream-ordered before st_main)
    if (bx == 0) {
        for (int i = threadIdx.x; i < NB * 4; i += 128) (&g_fP0q[0][0])[i] = 0;
        for (int i = threadIdx.x; i < 2 * TOUT * NB * 4; i += 128) (&g_fcell[0][0][0][0])[i] = 0;
        if (threadIdx.x == 0) { g_qwf = 0; g_qpp = 0; }
    }
}

__global__ void prep_rows(const float* __restrict__ hs, const float* __restrict__ cs,
                          const float* __restrict__ gts) {
    int i = blockIdx.x * blockDim.x + threadIdx.x;
    const int total = NB * BB * HH;
    if (i >= total) return;
    int h = i % HH;
    int b = (i / HH) % BB;
    int j = i / (HH * BB);
    const float* ph = hs + (b * TIN * NB + j) * HH + h;
    const float* pc = cs + (b * TIN * NB + j) * HH + h;
    float sh = 0.f, sc = 0.f;
    for (int t = 0; t < TIN; t++) { sh += ph[t * NB * HH]; sc += pc[t * NB * HH]; }
    float gv = gts[(b * NB + j) * HH + h];
    float r0 = sh / 49.0f, r1 = (sh + gv) / 50.0f;
    int o0 = (0 * NB + j) * BB * HH + b * HH + h;
    int o1 = (1 * NB + j) * BB * HH + b * HH + h;
    g_rowh[o0] = r0; g_rowh[o1] = r1;
    g_rowh_r[o0] = f2tf32f(r0);
    g_rowh_r[o1] = f2tf32f(r1);
    g_rowc[j * BB * HH + b * HH + h] = sc / 49.0f;
}

__global__ void prep_cols() {
    int i = blockIdx.x * blockDim.x + threadIdx.x;
    if (i >= BB * HH) return;
    float sh = 0.f, sc = 0.f;
    for (int j = 0; j < NB; j++) {
        sh += g_rowh[j * BB * HH + i];
        sc += g_rowc[j * BB * HH + i];
    }
    g_colh_r[i] = f2tf32f(sh / (float)NB);
    g_colc[i] = sc / (float)NB;
}

// =====================================================================
// persistent kernel: two queues; CTA 128 thr (4 warps 2Mx2N), tile M=64 x N=160.
// K64 A-staging, B via per-gate LDG.128 (low reg pressure), occ 3.
// =====================================================================
#define WF_AS 68
#define WF_STAGE (64 * WF_AS)             // 4352 floats
#define WF_SMEM (3 * WF_STAGE * 4)        // 52224 B

__device__ __forceinline__ void issueA64(const float* __restrict__ asrc, int astr, int hoff,
                                         float* As) {
    const int tid = threadIdx.x;
#pragma unroll
    for (int i = 0; i < 8; i++) {   // 64 rows x 16 float4 over 128 thr
        int idx = tid + (i << 7);
        int r = idx >> 4;
        int c4 = (idx & 15) << 2;
        cp16(As + r * WF_AS + c4, asrc + r * astr + hoff + c4);
    }
}

template <bool CVT>
__device__ __forceinline__ void compute_sub(const float* Asf, int cb, const float4* wc,
                                            int bo4, int wm, int wn, int g, int tg,
                                            float acc[2][10][4]) {
    unsigned av[4][2][4];
#pragma unroll
    for (int ks = 0; ks < 4; ks++) {
        int col = cb + (ks << 3) + tg;
#pragma unroll
        for (int mi = 0; mi < 2; mi++) {
            int row = (wm << 5) + (mi << 4) + g;
            if (CVT) {
                av[ks][mi][0] = f2tf32(Asf[row * WF_AS + col]);
                av[ks][mi][1] = f2tf32(Asf[(row + 8) * WF_AS + col]);
                av[ks][mi][2] = f2tf32(Asf[row * WF_AS + col + 4]);
                av[ks][mi][3] = f2tf32(Asf[(row + 8) * WF_AS + col + 4]);
            } else {
                const unsigned* Asu = (const unsigned*)Asf;
                av[ks][mi][0] = Asu[row * WF_AS + col];
                av[ks][mi][1] = Asu[(row + 8) * WF_AS + col];
                av[ks][mi][2] = Asu[row * WF_AS + col + 4];
                av[ks][mi][3] = Asu[(row + 8) * WF_AS + col + 4];
            }
        }
    }
#pragma unroll
    for (int par = 0; par < 2; par++) {
#pragma unroll
        for (int gate = 0; gate < 5; gate++) {
            int fo = bo4 + (gate << 8) + (par << 6);
            float4 b0 = __ldg(wc + fo);
            float4 b1 = __ldg(wc + fo + 1);
            int f = gate * 2 + par;
#pragma unroll
            for (int mi = 0; mi < 2; mi++) {
                mma_tf32(acc[mi][f], av[0][mi], __float_as_uint(b0.x), __float_as_uint(b0.y));
                mma_tf32(acc[mi][f], av[1][mi], __float_as_uint(b0.z), __float_as_uint(b0.w));
                mma_tf32(acc[mi][f], av[2][mi], __float_as_uint(b1.x), __float_as_uint(b1.y));
                mma_tf32(acc[mi][f], av[3][mi], __float_as_uint(b1.z), __float_as_uint(b1.w));
            }
        }
    }
}

// ---- prepass tile ----
__device__ void pp_tile(int j, int rem, const float* __restrict__ p, float* smem) {
    int rtile = rem >> 2;
    int r0 = rtile << 6;
    int ht = rem & 3;

    const int tid = threadIdx.x;
    const int warp = tid >> 5, lane = tid & 31;
    const int wm = warp >> 1, wn = warp & 1;
    const int g = lane >> 2, tg = lane & 3;

    const float* asrc = p + (r0 * NB + j) * HH;
    const int astr = NB * HH;
    const float4* wbase = (const float4*)(g_Wfrag + ((size_t)(j * 12) * 4 + ht) * WCHUNK_FLOATS);
    const int bo4 = ((wn * 16 + g) << 3) + (tg << 1);

    float acc[2][10][4];
#pragma unroll
    for (int i = 0; i < 2; i++)
#pragma unroll
        for (int f = 0; f < 10; f++)
#pragma unroll
            for (int ci = 0; ci < 4; ci++) acc[i][f][ci] = 0.0f;

    issueA64(asrc, astr, 0, smem); cp_commit();
    issueA64(asrc, astr, 64, smem + WF_STAGE); cp_commit();

    for (int c = 0; c < 2; c++) {  // 2 K64 chunks (K=128)
        cp_wait<1>();
        __syncthreads();
        cp_commit();
        const float* Asf = smem + c * WF_STAGE;
#pragma unroll
        for (int sub = 0; sub < 2; sub++) {
            int q = 2 * c + sub;
            compute_sub<true>(Asf, sub << 5, wbase + (size_t)q * WCHUNK_FLOATS,
                              bo4, wm, wn, g, tg, acc);
        }
    }

#pragma unroll
    for (int mi = 0; mi < 2; mi++)
#pragma unroll
        for (int rs = 0; rs < 2; rs++) {
            int r1 = r0 + (wm << 5) + (mi << 4) + g + (rs << 3);
            int ci = rs << 1;
#pragma unroll
            for (int par = 0; par < 2; par++) {
                int nloc = ht * 32 + wn * 16 + par * 8 + (tg << 1);
#pragma unroll
                for (int gate = 0; gate < 5; gate++) {
                    int f = gate * 2 + par;
                    *(float2*)(g_P0 + (size_t)(r1 * NB + j) * FIVEH + gate * 128 + nloc) =
                        make_float2(acc[mi][f][ci], acc[mi][f][ci + 1]);
                }
            }
        }

    __threadfence();
    __syncthreads();
    if (tid == 0) atomicAdd(&g_fP0q[j][rtile / 25], 1);
}

// ---- wavefront tile ----
__device__ void process_cell_tile(int t, int j, int l, int mtile, int htile,
                                  const float* __restrict__ bias,
                                  float* __restrict__ outh, float* __restrict__ outc,
                                  float* smem) {
    const int tid = threadIdx.x;
    const int warp = tid >> 5, lane = tid & 31;
    const int wm = warp >> 1, wn = warp & 1;
    const int g = lane >> 2, tg = lane & 3;
    const int b0 = mtile << 6;
    const int h0 = htile << 5;
    const int lj = l * NB + j;
    const int nc = (l == 0) ? 4 : 6;     // K64 chunks
    const int kc0 = (l == 0) ? 4 : 0;

    // ---- dataflow waits: threads 0..2 poll their flag concurrently ----
    if (tid < 3) {
        const int* f = 0; int tgt = 0;
        if (l == 0) {
            if (tid == 0 && t > 0) { f = &g_fcell[0][t - 1][j][mtile]; tgt = 4; }
            if (tid == 1 && j > 0) { f = &g_fcell[0][t][j - 1][mtile]; tgt = 4; }
            if (tid == 2)          { f = &g_fP0q[j][mtile]; tgt = 100; }
        } else {
            if (tid == 0)          { f = &g_fcell[0][t][j][mtile]; tgt = 4; }
            if (tid == 1 && t > 0) { f = &g_fcell[1][t - 1][j][mtile]; tgt = 4; }
            if (tid == 2 && j > 0) { f = &g_fcell[1][t][j - 1][mtile]; tgt = 4; }
        }
        if (f) spin_flag(f, tgt);
    }
    __syncthreads();

    const float* srcs[3];
    if (l == 0) {
        srcs[0] = (t == 0) ? g_rowh_r + ((0 * NB + j) * BB + b0) * HH
                           : g_h0 + (((t - 1) * NB + j) * BB + b0) * HH;
        srcs[1] = (j == 0) ? g_colh_r + b0 * HH
                           : g_h0 + ((t * NB + (j - 1)) * BB + b0) * HH;
        srcs[2] = srcs[1];
    } else {
        srcs[0] = g_h0 + ((t * NB + j) * BB + b0) * HH;
        srcs[1] = (t == 0) ? g_rowh_r + ((1 * NB + j) * BB + b0) * HH
                           : g_h1r + (((t - 1) * NB + j) * BB + b0) * HH;
        srcs[2] = (j == 0) ? g_colh_r + b0 * HH
                           : g_h1r + ((t * NB + (j - 1)) * BB + b0) * HH;
    }

    const float4* wbase = (const float4*)(g_Wfrag + ((size_t)(lj * 12 + kc0) * 4 + htile) * WCHUNK_FLOATS);
    const int bo4 = ((wn * 16 + g) << 3) + (tg << 1);

    float acc[2][10][4];
#pragma unroll
    for (int i = 0; i < 2; i++)
#pragma unroll
        for (int f = 0; f < 10; f++)
#pragma unroll
            for (int ci = 0; ci < 4; ci++) acc[i][f][ci] = 0.0f;

    issueA64(srcs[0], HH, 0, smem); cp_commit();
    issueA64(srcs[0], HH, 64, smem + WF_STAGE); cp_commit();

    for (int c = 0; c < nc; c++) {
        cp_wait<1>();
        __syncthreads();
        int nx = c + 2;
        if (nx < nc) issueA64(srcs[nx >> 1], HH, (nx & 1) << 6, smem + (nx % 3) * WF_STAGE);
        cp_commit();

        const float* Asf = smem + (c % 3) * WF_STAGE;
#pragma unroll
        for (int sub = 0; sub < 2; sub++) {
            int q = 2 * c + sub;
            compute_sub<false>(Asf, sub << 5, wbase + (size_t)q * WCHUNK_FLOATS,
                               bo4, wm, wn, g, tg, acc);
        }
    }

    // ---- register epilogue (direct c-state loads; L2-hot) ----
    const float* brow = bias + lj * FIVEH;
    const float* ctp; int cts;
    if (t == 0)      { ctp = g_rowc + (j * BB + b0) * HH; cts = HH; }
    else if (l == 0) { ctp = g_c0 + (((t - 1) * NB + j) * BB + b0) * HH; cts = HH; }
    else             { ctp = outc + ((b0 * TOUT + (t - 1)) * NB + j) * HH; cts = TOUT * NB * HH; }
    const float* csp; int css;
    if (j == 0)      { csp = g_colc + b0 * HH; css = HH; }
    else if (l == 0) { csp = g_c0 + ((t * NB + (j - 1)) * BB + b0) * HH; css = HH; }
    else             { csp = outc + ((b0 * TOUT + t) * NB + (j - 1)) * HH; css = TOUT * NB * HH; }

#pragma unroll
    for (int mi = 0; mi < 2; mi++)
#pragma unroll
        for (int rs = 0; rs < 2; rs++) {
            int m = (wm << 5) + (mi << 4) + g + (rs << 3);
            int ci = rs << 1;
            const float* ctr = ctp + m * cts;
            const float* csr = csp + m * css;
#pragma unroll
            for (int par = 0; par < 2; par++) {
                int ha = h0 + wn * 16 + par * 8 + (tg << 1);
                float z[5][2];
#pragma unroll
                for (int gate = 0; gate < 5; gate++) {
                    int f = gate * 2 + par;
                    z[gate][0] = acc[mi][f][ci];
                    z[gate][1] = acc[mi][f][ci + 1];
                }
                if (l == 0) {
                    const float* p0 = g_P0 + (size_t)(((b0 + m) * TOUT + t) * NB + j) * FIVEH;
#pragma unroll
                    for (int gate = 0; gate < 5; gate++) {
                        float2 pv = *(const float2*)(p0 + gate * 128 + ha);
                        z[gate][0] += pv.x; z[gate][1] += pv.y;
                    }
                }
#pragma unroll
                for (int gate = 0; gate < 5; gate++) {
                    float2 bv = *(const float2*)(brow + gate * 128 + ha);
                    z[gate][0] += bv.x; z[gate][1] += bv.y;
                }
                float2 ctv = *(const float2*)(ctr + ha);
                float2 csv = *(const float2*)(csr + ha);
                float cv0 = sigm(z[0][0]) * tanh_fast(z[4][0]) + sigm(z[2][0]) * ctv.x + sigm(z[1][0]) * csv.x;
                float cv1 = sigm(z[0][1]) * tanh_fast(z[4][1]) + sigm(z[2][1]) * ctv.y + sigm(z[1][1]) * csv.y;
                float hv0 = sigm(z[3][0]) * tanh_fast(cv0);
                float hv1 = sigm(z[3][1]) * tanh_fast(cv1);
                if (l == 0) {
                    size_t off = (size_t)((t * NB + j) * BB + b0 + m) * HH + ha;
                    *(float2*)(g_h0 + off) = make_float2(f2tf32f(hv0), f2tf32f(hv1));
                    *(float2*)(g_c0 + off) = make_float2(cv0, cv1);
                } else {
                    size_t oo = (size_t)(((b0 + m) * TOUT + t) * NB + j) * HH + ha;
                    *(float2*)(outh + oo) = make_float2(hv0, hv1);
                    *(float2*)(outc + oo) = make_float2(cv0, cv1);
                    size_t so = (size_t)((t * NB + j) * BB + b0 + m) * HH + ha;
                    *(float2*)(g_h1r + so) = make_float2(f2tf32f(hv0), f2tf32f(hv1));
                }
            }
        }

    __threadfence();
    __syncthreads();
    if (tid == 0) atomicAdd(&g_fcell[l][t][j][mtile], 1);
}

// decode wavefront item index (diagonal-topo order) -> (l,t,j,mt,ht)
__device__ __forceinline__ void decode_wf(int idx, int& l, int& t, int& j, int& mt, int& ht) {
    int base = 0;
    for (int d = 0; d < 49; d++) {
        int lo0 = (d - 23 > 0) ? d - 23 : 0;
        int hi0 = (d < 24) ? d : 24;
        int n0 = hi0 - lo0 + 1;
        int n1 = 0, lo1 = 0;
        if (d >= 1) {
            int e = d - 1;
            lo1 = (e - 23 > 0) ? e - 23 : 0;
            int hi1 = (e < 24) ? e : 24;
            n1 = hi1 - lo1 + 1;
        }
        int wf = (n0 + n1) << 4;
        if (idx < base + wf) {
            int it = idx - base;
            int cell = it >> 4;
            if (cell < n0) { l = 0; t = lo0 + cell; j = d - t; }
            else           { l = 1; t = lo1 + (cell - n0); j = (d - 1) - t; }
            mt = (it >> 2) & 3; ht = it & 3;
            return;
        }
        base += wf;
    }
}

__global__ void __launch_bounds__(128, 3)
st_main(const float* __restrict__ p, const float* __restrict__ bias,
        float* __restrict__ outh, float* __restrict__ outc) {
    extern __shared__ float smem[];
    __shared__ int s_item;

    // bulk CTAs: drain prepass queue first
    if (blockIdx.x >= WF_CTAS) {
        for (;;) {
            if (threadIdx.x == 0) s_item = atomicAdd(&g_qpp, 1);
            __syncthreads();
            int idx = s_item;
            if (idx >= NPP) break;
            pp_tile(idx / 400, idx % 400, p, smem);
        }
    }

    // all CTAs: wavefront queue (topo order)
    for (;;) {
        if (threadIdx.x == 0) s_item = atomicAdd(&g_qwf, 1);
        __syncthreads();
        int idx = s_item;
        if (idx >= NWF) break;
        int l, t, j, mt, ht;
        decode_wf(idx, l, t, j, mt, ht);
        process_cell_tile(t, j, l, mt, ht, bias, outh, outc, smem);
    }
}

// ---------------- launch ----------------
extern "C" void kernel_launch(void* const* d_in, const int* in_sizes, int n_in,
                              void* d_out, int out_size) {
    const float* hs = (const float*)d_in[0];
    const float* cs = (const float*)d_in[1];
    const float* gts = (const float*)d_in[2];
    const float* p = (const float*)d_in[3];
    const float* U = (const float*)d_in[4];
    const float* Wt = (const float*)d_in[5];
    const float* Ws = (const float*)d_in[6];
    const float* b = (const float*)d_in[7];

    float* outh = (float*)d_out;
    float* outc = outh + (size_t)BB * TOUT * NB * HH;

    prep_wfrag<<<11520, 128>>>(U, Wt, Ws);          // also zeroes flags/queues (block 0)
    prep_rows<<<(NB * BB * HH + 255) / 256, 256>>>(hs, cs, gts);
    prep_cols<<<(BB * HH + 255) / 256, 256>>>();

    int dev = 0;
    cudaGetDevice(&dev);
    int nsm = 148;
    cudaDeviceGetAttribute(&nsm, cudaDevAttrMultiProcessorCount, dev);
    cudaFuncSetAttribute(st_main, cudaFuncAttributeMaxDynamicSharedMemorySize, WF_SMEM);
    int occ = 0;
    cudaOccupancyMaxActiveBlocksPerMultiprocessor(&occ, st_main, 128, WF_SMEM);
    if (occ < 1) occ = 1;
    if (occ > 3) occ = 3;
    st_main<<<nsm * occ, 128, WF_SMEM>>>(p, b, outh, outc);
}

// round 17
// speedup vs baseline: 1.0110x; 1.0110x over previous
#include <cuda_runtime.h>
#include <math.h>

#define BB 256
#define TIN 49
#define TOUT 25
#define NB 24
#define HH 128
#define FIVEH 640
#define KTOT 384

#define WCHUNK_FLOATS 5120  // one (lj,kc32,ht) B chunk: 5 gates x 32 cols x 4 tg x 8 s
#define NPP (NB * 400)      // 9600 prepass items
#define NWF 19200           // wavefront items
#define WF_CTAS 96          // dedicated chain-runner CTAs

// ---------------- device scratch ----------------
__device__ float g_Wfrag[48 * 12 * 4 * WCHUNK_FLOATS];   // 45 MB fragment weights
__device__ float g_P0[BB * TOUT * NB * FIVEH];
__device__ float g_h0[TOUT * NB * BB * HH];       // layer-0 h (tf32-rounded)
__device__ float g_c0[TOUT * NB * BB * HH];       // layer-0 c (full)
__device__ float g_h1r[TOUT * NB * BB * HH];      // layer-1 h rounded shadow
__device__ float g_rowh[2 * NB * BB * HH];
__device__ float g_rowh_r[2 * NB * BB * HH];
__device__ float g_rowc[NB * BB * HH];
__device__ float g_colh_r[BB * HH];
__device__ float g_colc[BB * HH];
// dataflow state
__device__ int g_fP0q[NB][4];             // per (j, b-quarter), target 100
__device__ int g_fcell[2][TOUT][NB][4];   // [l][t][j][mt], target 4
__device__ int g_qwf;
__device__ int g_qpp;

// ---------------- helpers ----------------
__device__ __forceinline__ float sigm(float x) { return 1.0f / (1.0f + __expf(-x)); }
__device__ __forceinline__ float tanh_fast(float x) { return 2.0f / (1.0f + __expf(-2.0f * x)) - 1.0f; }

__device__ __forceinline__ unsigned f2tf32(float v) {
    unsigned u;
    asm("cvt.rna.tf32.f32 %0, %1;" : "=r"(u) : "f"(v));
    return u;
}
__device__ __forceinline__ float f2tf32f(float v) { return __uint_as_float(f2tf32(v)); }

__device__ __forceinline__ void mma_tf32(float* c, const unsigned* a, unsigned b0, unsigned b1) {
    asm volatile(
        "mma.sync.aligned.m16n8k8.row.col.f32.tf32.tf32.f32 "
        "{%0,%1,%2,%3}, {%4,%5,%6,%7}, {%8,%9}, {%0,%1,%2,%3};\n"
        : "+f"(c[0]), "+f"(c[1]), "+f"(c[2]), "+f"(c[3])
        : "r"(a[0]), "r"(a[1]), "r"(a[2]), "r"(a[3]), "r"(b0), "r"(b1));
}

__device__ __forceinline__ void cp16(float* dst_smem, const float* src_gmem) {
    unsigned d = (unsigned)__cvta_generic_to_shared(dst_smem);
    asm volatile("cp.async.cg.shared.global [%0], [%1], 16;\n" ::"r"(d), "l"(src_gmem));
}
__device__ __forceinline__ void cp_commit() { asm volatile("cp.async.commit_group;\n"); }
template <int N>
__device__ __forceinline__ void cp_wait() { asm volatile("cp.async.wait_group %0;\n" ::"n"(N)); }

__device__ __forceinline__ void spin_flag(const int* f, int target) {
    while (*(volatile const int*)f < target) __nanosleep(20);
}

// ---------------- prep: fragment-major weight pack (+ flag zeroing in block 0) ----------------
__global__ void prep_wfrag(const float* __restrict__ U, const float* __restrict__ Wt,
                           const float* __restrict__ Ws) {
    __shared__ float tile[32][33];
    int bx = blockIdx.x;
    int gate = bx % 5;
    int ht = (bx / 5) & 3;
    int kc = (bx / 20) % 12;
    int lj = bx / 240;
    int tx = threadIdx.x & 31, ty = threadIdx.x >> 5;

    const float* src;
    int kbase;
    if (kc < 4) { src = U; kbase = kc * 32; }
    else if (kc < 8) { src = Wt; kbase = (kc - 4) * 32; }
    else { src = Ws; kbase = (kc - 8) * 32; }
    int n0 = gate * 128 + ht * 32;

    for (int kk = ty; kk < 32; kk += 4) {
        float v = src[((size_t)lj * HH + kbase + kk) * FIVEH + n0 + tx];
        tile[kk][tx] = f2tf32f(v);
    }
    __syncthreads();
    float* out = g_Wfrag + ((size_t)(lj * 12 + kc) * 4 + ht) * WCHUNK_FLOATS + gate * 1024;
    int q = tx;
    int kk = (q >> 3) + ((q & 7) << 2);  // tg = q>>3, s = q&7, k-row = tg + 4s
    for (int hh = ty; hh < 32; hh += 4) {
        out[hh * 32 + q] = tile[kk][hh];
    }
    // block 0 zeroes dataflow state (stream-ordered before st_main)
    if (bx == 0) {
        for (int i = threadIdx.x; i < NB * 4; i += 128) (&g_fP0q[0][0])[i] = 0;
        for (int i = threadIdx.x; i < 2 * TOUT * NB * 4; i += 128) (&g_fcell[0][0][0][0])[i] = 0;
        if (threadIdx.x == 0) { g_qwf = 0; g_qpp = 0; }
    }
}

__global__ void prep_rows(const float* __restrict__ hs, const float* __restrict__ cs,
                          const float* __restrict__ gts) {
    int i = blockIdx.x * blockDim.x + threadIdx.x;
    const int total = NB * BB * HH;
    if (i >= total) return;
    int h = i % HH;
    int b = (i / HH) % BB;
    int j = i / (HH * BB);
    const float* ph = hs + (b * TIN * NB + j) * HH + h;
    const float* pc = cs + (b * TIN * NB + j) * HH + h;
    float sh = 0.f, sc = 0.f;
    for (int t = 0; t < TIN; t++) { sh += ph[t * NB * HH]; sc += pc[t * NB * HH]; }
    float gv = gts[(b * NB + j) * HH + h];
    float r0 = sh / 49.0f, r1 = (sh + gv) / 50.0f;
    int o0 = (0 * NB + j) * BB * HH + b * HH + h;
    int o1 = (1 * NB + j) * BB * HH + b * HH + h;
    g_rowh[o0] = r0; g_rowh[o1] = r1;
    g_rowh_r[o0] = f2tf32f(r0);
    g_rowh_r[o1] = f2tf32f(r1);
    g_rowc[j * BB * HH + b * HH + h] = sc / 49.0f;
}

__global__ void prep_cols() {
    int i = blockIdx.x * blockDim.x + threadIdx.x;
    if (i >= BB * HH) return;
    float sh = 0.f, sc = 0.f;
    for (int j = 0; j < NB; j++) {
        sh += g_rowh[j * BB * HH + i];
        sc += g_rowc[j * BB * HH + i];
    }
    g_colh_r[i] = f2tf32f(sh / (float)NB);
    g_colc[i] = sc / (float)NB;
}

// =====================================================================
// persistent kernel: two queues; CTA 128 thr (4 warps 2Mx2N), tile M=64 x N=160.
// K64 A-staging; B register-pipelined at par-block granularity (2x40-float bufs),
// first two par-blocks prefetched BEFORE the dependency spin.
// =====================================================================
#define WF_AS 68
#define WF_STAGE (64 * WF_AS)             // 4352 floats
#define WF_SMEM (3 * WF_STAGE * 4)        // 52224 B

__device__ __forceinline__ void issueA64(const float* __restrict__ asrc, int astr, int hoff,
                                         float* As) {
    const int tid = threadIdx.x;
#pragma unroll
    for (int i = 0; i < 8; i++) {   // 64 rows x 16 float4 over 128 thr
        int idx = tid + (i << 7);
        int r = idx >> 4;
        int c4 = (idx & 15) << 2;
        cp16(As + r * WF_AS + c4, asrc + r * astr + hoff + c4);
    }
}

__device__ __forceinline__ void ldB(float4* bq, const float4* wc, int bo4, int par) {
#pragma unroll
    for (int gate = 0; gate < 5; gate++) {
        int fo = bo4 + (gate << 8) + (par << 6);
        bq[gate * 2] = __ldg(wc + fo);
        bq[gate * 2 + 1] = __ldg(wc + fo + 1);
    }
}

__device__ __forceinline__ void loadAv(const float* Asf, int cb, int wm, int g, int tg,
                                       unsigned av[4][2][4]) {
    const unsigned* Asu = (const unsigned*)Asf;
#pragma unroll
    for (int ks = 0; ks < 4; ks++) {
        int col = cb + (ks << 3) + tg;
#pragma unroll
        for (int mi = 0; mi < 2; mi++) {
            int row = (wm << 5) + (mi << 4) + g;
            av[ks][mi][0] = Asu[row * WF_AS + col];
            av[ks][mi][1] = Asu[(row + 8) * WF_AS + col];
            av[ks][mi][2] = Asu[row * WF_AS + col + 4];
            av[ks][mi][3] = Asu[(row + 8) * WF_AS + col + 4];
        }
    }
}

__device__ __forceinline__ void compute_pb(float acc[2][10][4], unsigned av[4][2][4],
                                           const float4* bq, int par) {
#pragma unroll
    for (int gate = 0; gate < 5; gate++) {
        int f = gate * 2 + par;
        float4 b0 = bq[gate * 2], b1 = bq[gate * 2 + 1];
#pragma unroll
        for (int mi = 0; mi < 2; mi++) {
            mma_tf32(acc[mi][f], av[0][mi], __float_as_uint(b0.x), __float_as_uint(b0.y));
            mma_tf32(acc[mi][f], av[1][mi], __float_as_uint(b0.z), __float_as_uint(b0.w));
            mma_tf32(acc[mi][f], av[2][mi], __float_as_uint(b1.x), __float_as_uint(b1.y));
            mma_tf32(acc[mi][f], av[3][mi], __float_as_uint(b1.z), __float_as_uint(b1.w));
        }
    }
}

// legacy combined path (prepass only; cvt at consume)
template <bool CVT>
__device__ __forceinline__ void compute_sub(const float* Asf, int cb, const float4* wc,
                                            int bo4, int wm, int wn, int g, int tg,
                                            float acc[2][10][4]) {
    unsigned av[4][2][4];
#pragma unroll
    for (int ks = 0; ks < 4; ks++) {
        int col = cb + (ks << 3) + tg;
#pragma unroll
        for (int mi = 0; mi < 2; mi++) {
            int row = (wm << 5) + (mi << 4) + g;
            if (CVT) {
                av[ks][mi][0] = f2tf32(Asf[row * WF_AS + col]);
                av[ks][mi][1] = f2tf32(Asf[(row + 8) * WF_AS + col]);
                av[ks][mi][2] = f2tf32(Asf[row * WF_AS + col + 4]);
                av[ks][mi][3] = f2tf32(Asf[(row + 8) * WF_AS + col + 4]);
            } else {
                const unsigned* Asu = (const unsigned*)Asf;
                av[ks][mi][0] = Asu[row * WF_AS + col];
                av[ks][mi][1] = Asu[(row + 8) * WF_AS + col];
                av[ks][mi][2] = Asu[row * WF_AS + col + 4];
                av[ks][mi][3] = Asu[(row + 8) * WF_AS + col + 4];
            }
        }
    }
#pragma unroll
    for (int par = 0; par < 2; par++) {
#pragma unroll
        for (int gate = 0; gate < 5; gate++) {
            int fo = bo4 + (gate << 8) + (par << 6);
            float4 b0 = __ldg(wc + fo);
            float4 b1 = __ldg(wc + fo + 1);
            int f = gate * 2 + par;
#pragma unroll
            for (int mi = 0; mi < 2; mi++) {
                mma_tf32(acc[mi][f], av[0][mi], __float_as_uint(b0.x), __float_as_uint(b0.y));
                mma_tf32(acc[mi][f], av[1][mi], __float_as_uint(b0.z), __float_as_uint(b0.w));
                mma_tf32(acc[mi][f], av[2][mi], __float_as_uint(b1.x), __float_as_uint(b1.y));
                mma_tf32(acc[mi][f], av[3][mi], __float_as_uint(b1.z), __float_as_uint(b1.w));
            }
        }
    }
}

// ---- prepass tile ----
__device__ void pp_tile(int j, int rem, const float* __restrict__ p, float* smem) {
    int rtile = rem >> 2;
    int r0 = rtile << 6;
    int ht = rem & 3;

    const int tid = threadIdx.x;
    const int warp = tid >> 5, lane = tid & 31;
    const int wm = warp >> 1, wn = warp & 1;
    const int g = lane >> 2, tg = lane & 3;

    const float* asrc = p + (r0 * NB + j) * HH;
    const int astr = NB * HH;
    const float4* wbase = (const float4*)(g_Wfrag + ((size_t)(j * 12) * 4 + ht) * WCHUNK_FLOATS);
    const int bo4 = ((wn * 16 + g) << 3) + (tg << 1);

    float acc[2][10][4];
#pragma unroll
    for (int i = 0; i < 2; i++)
#pragma unroll
        for (int f = 0; f < 10; f++)
#pragma unroll
            for (int ci = 0; ci < 4; ci++) acc[i][f][ci] = 0.0f;

    issueA64(asrc, astr, 0, smem); cp_commit();
    issueA64(asrc, astr, 64, smem + WF_STAGE); cp_commit();

    for (int c = 0; c < 2; c++) {  // 2 K64 chunks (K=128)
        cp_wait<1>();
        __syncthreads();
        cp_commit();
        const float* Asf = smem + c * WF_STAGE;
#pragma unroll
        for (int sub = 0; sub < 2; sub++) {
            int q = 2 * c + sub;
            compute_sub<true>(Asf, sub << 5, wbase + (size_t)q * WCHUNK_FLOATS,
                              bo4, wm, wn, g, tg, acc);
        }
    }

#pragma unroll
    for (int mi = 0; mi < 2; mi++)
#pragma unroll
        for (int rs = 0; rs < 2; rs++) {
            int r1 = r0 + (wm << 5) + (mi << 4) + g + (rs << 3);
            int ci = rs << 1;
#pragma unroll
            for (int par = 0; par < 2; par++) {
                int nloc = ht * 32 + wn * 16 + par * 8 + (tg << 1);
#pragma unroll
                for (int gate = 0; gate < 5; gate++) {
                    int f = gate * 2 + par;
                    *(float2*)(g_P0 + (size_t)(r1 * NB + j) * FIVEH + gate * 128 + nloc) =
                        make_float2(acc[mi][f][ci], acc[mi][f][ci + 1]);
                }
            }
        }

    __threadfence();
    __syncthreads();
    if (tid == 0) atomicAdd(&g_fP0q[j][rtile / 25], 1);
}

// ---- wavefront tile ----
__device__ void process_cell_tile(int t, int j, int l, int mtile, int htile,
                                  const float* __restrict__ bias,
                                  float* __restrict__ outh, float* __restrict__ outc,
                                  float* smem) {
    const int tid = threadIdx.x;
    const int warp = tid >> 5, lane = tid & 31;
    const int wm = warp >> 1, wn = warp & 1;
    const int g = lane >> 2, tg = lane & 3;
    const int b0 = mtile << 6;
    const int h0 = htile << 5;
    const int lj = l * NB + j;
    const int nc = (l == 0) ? 4 : 6;     // K64 chunks
    const int kc0 = (l == 0) ? 4 : 0;

    const float4* wbase = (const float4*)(g_Wfrag + ((size_t)(lj * 12 + kc0) * 4 + htile) * WCHUNK_FLOATS);
    const int bo4 = ((wn * 16 + g) << 3) + (tg << 1);

    // ---- B register pipeline: prefetch par-blocks 0,1 BEFORE the spin ----
    float4 bq0[10], bq1[10];
    ldB(bq0, wbase, bo4, 0);
    ldB(bq1, wbase, bo4, 1);

    // ---- dataflow waits: threads 0..2 poll their flag concurrently ----
    if (tid < 3) {
        const int* f = 0; int tgt = 0;
        if (l == 0) {
            if (tid == 0 && t > 0) { f = &g_fcell[0][t - 1][j][mtile]; tgt = 4; }
            if (tid == 1 && j > 0) { f = &g_fcell[0][t][j - 1][mtile]; tgt = 4; }
            if (tid == 2)          { f = &g_fP0q[j][mtile]; tgt = 100; }
        } else {
            if (tid == 0)          { f = &g_fcell[0][t][j][mtile]; tgt = 4; }
            if (tid == 1 && t > 0) { f = &g_fcell[1][t - 1][j][mtile]; tgt = 4; }
            if (tid == 2 && j > 0) { f = &g_fcell[1][t][j - 1][mtile]; tgt = 4; }
        }
        if (f) spin_flag(f, tgt);
    }
    __syncthreads();

    const float* srcs[3];
    if (l == 0) {
        srcs[0] = (t == 0) ? g_rowh_r + ((0 * NB + j) * BB + b0) * HH
                           : g_h0 + (((t - 1) * NB + j) * BB + b0) * HH;
        srcs[1] = (j == 0) ? g_colh_r + b0 * HH
                           : g_h0 + ((t * NB + (j - 1)) * BB + b0) * HH;
        srcs[2] = srcs[1];
    } else {
        srcs[0] = g_h0 + ((t * NB + j) * BB + b0) * HH;
        srcs[1] = (t == 0) ? g_rowh_r + ((1 * NB + j) * BB + b0) * HH
                           : g_h1r + (((t - 1) * NB + j) * BB + b0) * HH;
        srcs[2] = (j == 0) ? g_colh_r + b0 * HH
                           : g_h1r + ((t * NB + (j - 1)) * BB + b0) * HH;
    }

    float acc[2][10][4];
#pragma unroll
    for (int i = 0; i < 2; i++)
#pragma unroll
        for (int f = 0; f < 10; f++)
#pragma unroll
            for (int ci = 0; ci < 4; ci++) acc[i][f][ci] = 0.0f;

    issueA64(srcs[0], HH, 0, smem); cp_commit();
    issueA64(srcs[0], HH, 64, smem + WF_STAGE); cp_commit();

    const int pbmax = nc << 2;   // par-blocks total (16 or 24)
    for (int c = 0; c < nc; c++) {
        cp_wait<1>();
        __syncthreads();
        int nx = c + 2;
        if (nx < nc) issueA64(srcs[nx >> 1], HH, (nx & 1) << 6, smem + (nx % 3) * WF_STAGE);
        cp_commit();

        const float* Asf = smem + (c % 3) * WF_STAGE;
#pragma unroll
        for (int sub = 0; sub < 2; sub++) {
            unsigned av[4][2][4];
            loadAv(Asf, sub << 5, wm, g, tg, av);
#pragma unroll
            for (int par = 0; par < 2; par++) {
                int q = (c << 2) + (sub << 1) + par;   // parity(q) == par
                if (par == 0) {
                    compute_pb(acc, av, bq0, 0);
                    int qq = q + 2;
                    if (qq < pbmax) ldB(bq0, wbase + (size_t)(qq >> 1) * WCHUNK_FLOATS, bo4, 0);
                } else {
                    compute_pb(acc, av, bq1, 1);
                    int qq = q + 2;
                    if (qq < pbmax) ldB(bq1, wbase + (size_t)(qq >> 1) * WCHUNK_FLOATS, bo4, 1);
                }
            }
        }
    }

    // ---- register epilogue (direct c-state loads; L2-hot) ----
    const float* brow = bias + lj * FIVEH;
    const float* ctp; int cts;
    if (t == 0)      { ctp = g_rowc + (j * BB + b0) * HH; cts = HH; }
    else if (l == 0) { ctp = g_c0 + (((t - 1) * NB + j) * BB + b0) * HH; cts = HH; }
    else             { ctp = outc + ((b0 * TOUT + (t - 1)) * NB + j) * HH; cts = TOUT * NB * HH; }
    const float* csp; int css;
    if (j == 0)      { csp = g_colc + b0 * HH; css = HH; }
    else if (l == 0) { csp = g_c0 + ((t * NB + (j - 1)) * BB + b0) * HH; css = HH; }
    else             { csp = outc + ((b0 * TOUT + t) * NB + (j - 1)) * HH; css = TOUT * NB * HH; }

#pragma unroll
    for (int mi = 0; mi < 2; mi++)
#pragma unroll
        for (int rs = 0; rs < 2; rs++) {
            int m = (wm << 5) + (mi << 4) + g + (rs << 3);
            int ci = rs << 1;
            const float* ctr = ctp + m * cts;
            const float* csr = csp + m * css;
#pragma unroll
            for (int par = 0; par < 2; par++) {
                int ha = h0 + wn * 16 + par * 8 + (tg << 1);
                float z[5][2];
#pragma unroll
                for (int gate = 0; gate < 5; gate++) {
                    int f = gate * 2 + par;
                    z[gate][0] = acc[mi][f][ci];
                    z[gate][1] = acc[mi][f][ci + 1];
                }
                if (l == 0) {
                    const float* p0 = g_P0 + (size_t)(((b0 + m) * TOUT + t) * NB + j) * FIVEH;
#pragma unroll
                    for (int gate = 0; gate < 5; gate++) {
                        float2 pv = *(const float2*)(p0 + gate * 128 + ha);
                        z[gate][0] += pv.x; z[gate][1] += pv.y;
                    }
                }
#pragma unroll
                for (int gate = 0; gate < 5; gate++) {
                    float2 bv = *(const float2*)(brow + gate * 128 + ha);
                    z[gate][0] += bv.x; z[gate][1] += bv.y;
                }
                float2 ctv = *(const float2*)(ctr + ha);
                float2 csv = *(const float2*)(csr + ha);
                float cv0 = sigm(z[0][0]) * tanh_fast(z[4][0]) + sigm(z[2][0]) * ctv.x + sigm(z[1][0]) * csv.x;
                float cv1 = sigm(z[0][1]) * tanh_fast(z[4][1]) + sigm(z[2][1]) * ctv.y + sigm(z[1][1]) * csv.y;
                float hv0 = sigm(z[3][0]) * tanh_fast(cv0);
                float hv1 = sigm(z[3][1]) * tanh_fast(cv1);
                if (l == 0) {
                    size_t off = (size_t)((t * NB + j) * BB + b0 + m) * HH + ha;
                    *(float2*)(g_h0 + off) = make_float2(f2tf32f(hv0), f2tf32f(hv1));
                    *(float2*)(g_c0 + off) = make_float2(cv0, cv1);
                } else {
                    size_t oo = (size_t)(((b0 + m) * TOUT + t) * NB + j) * HH + ha;
                    *(float2*)(outh + oo) = make_float2(hv0, hv1);
                    *(float2*)(outc + oo) = make_float2(cv0, cv1);
                    size_t so = (size_t)((t * NB + j) * BB + b0 + m) * HH + ha;
                    *(float2*)(g_h1r + so) = make_float2(f2tf32f(hv0), f2tf32f(hv1));
                }
            }
        }

    __threadfence();
    __syncthreads();
    if (tid == 0) atomicAdd(&g_fcell[l][t][j][mtile], 1);
}

// decode wavefront item index (diagonal-topo order) -> (l,t,j,mt,ht)
__device__ __forceinline__ void decode_wf(int idx, int& l, int& t, int& j, int& mt, int& ht) {
    int base = 0;
    for (int d = 0; d < 49; d++) {
        int lo0 = (d - 23 > 0) ? d - 23 : 0;
        int hi0 = (d < 24) ? d : 24;
        int n0 = hi0 - lo0 + 1;
        int n1 = 0, lo1 = 0;
        if (d >= 1) {
            int e = d - 1;
            lo1 = (e - 23 > 0) ? e - 23 : 0;
            int hi1 = (e < 24) ? e : 24;
            n1 = hi1 - lo1 + 1;
        }
        int wf = (n0 + n1) << 4;
        if (idx < base + wf) {
            int it = idx - base;
            int cell = it >> 4;
            if (cell < n0) { l = 0; t = lo0 + cell; j = d - t; }
            else           { l = 1; t = lo1 + (cell - n0); j = (d - 1) - t; }
            mt = (it >> 2) & 3; ht = it & 3;
            return;
        }
        base += wf;
    }
}

__global__ void __launch_bounds__(128)
st_main(const float* __restrict__ p, const float* __restrict__ bias,
        float* __restrict__ outh, float* __restrict__ outc) {
    extern __shared__ float smem[];
    __shared__ int s_item;

    // bulk CTAs: drain prepass queue first
    if (blockIdx.x >= WF_CTAS) {
        for (;;) {
            if (threadIdx.x == 0) s_item = atomicAdd(&g_qpp, 1);
            __syncthreads();
            int idx = s_item;
            if (idx >= NPP) break;
            pp_tile(idx / 400, idx % 400, p, smem);
        }
    }

    // all CTAs: wavefront queue (topo order)
    for (;;) {
        if (threadIdx.x == 0) s_item = atomicAdd(&g_qwf, 1);
        __syncthreads();
        int idx = s_item;
        if (idx >= NWF) break;
        int l, t, j, mt, ht;
        decode_wf(idx, l, t, j, mt, ht);
        process_cell_tile(t, j, l, mt, ht, bias, outh, outc, smem);
    }
}

// ---------------- launch ----------------
extern "C" void kernel_launch(void* const* d_in, const int* in_sizes, int n_in,
                              void* d_out, int out_size) {
    const float* hs = (const float*)d_in[0];
    const float* cs = (const float*)d_in[1];
    const float* gts = (const float*)d_in[2];
    const float* p = (const float*)d_in[3];
    const float* U = (const float*)d_in[4];
    const float* Wt = (const float*)d_in[5];
    const float* Ws = (const float*)d_in[6];
    const float* b = (const float*)d_in[7];

    float* outh = (float*)d_out;
    float* outc = outh + (size_t)BB * TOUT * NB * HH;

    prep_wfrag<<<11520, 128>>>(U, Wt, Ws);          // also zeroes flags/queues (block 0)
    prep_rows<<<(NB * BB * HH + 255) / 256, 256>>>(hs, cs, gts);
    prep_cols<<<(BB * HH + 255) / 256, 256>>>();

    int dev = 0;
    cudaGetDevice(&dev);
    int nsm = 148;
    cudaDeviceGetAttribute(&nsm, cudaDevAttrMultiProcessorCount, dev);
    cudaFuncSetAttribute(st_main, cudaFuncAttributeMaxDynamicSharedMemorySize, WF_SMEM);
    int occ = 0;
    cudaOccupancyMaxActiveBlocksPerMultiprocessor(&occ, st_main, 128, WF_SMEM);
    if (occ < 1) occ = 1;
    if (occ > 3) occ = 3;
    st_main<<<nsm * occ, 128, WF_SMEM>>>(p, b, outh, outc);
}